// round 1
// baseline (speedup 1.0000x reference)
#include <cuda_runtime.h>
#include <cuda_bf16.h>

#define DIM 128
#define HEADS 4
#define NMAX 50000

// ---- device scratch (static; no allocations) ----
__device__ float d_h[NMAX * DIM];        // x @ W_gat
__device__ float d_asrc[NMAX * HEADS];
__device__ float d_adst[NMAX * HEADS];
__device__ float d_denom[NMAX * HEADS];  // softmax denominators (atomic)
__device__ float d_deg[NMAX];            // in-degree (atomic)
__device__ float d_gacc[NMAX * DIM];     // unnormalized GAT accum -> gat_out (in place)
__device__ float d_sacc[NMAX * DIM];     // SAGE sum -> mean (in place)
__device__ float d_B[DIM * DIM];         // W_sage_l @ Wp2
__device__ float d_C[DIM * DIM];         // W_sage_r @ Wp2 + I
__device__ float d_dvec[DIM];            // b_sage_l @ Wp2 + b_proj
__device__ int d_is64;

__device__ __forceinline__ void red4(float* p, float a, float b, float c, float d) {
    asm volatile("red.global.add.v4.f32 [%0], {%1,%2,%3,%4};"
                 :: "l"(__cvta_generic_to_global(p)), "f"(a), "f"(b), "f"(c), "f"(d)
                 : "memory");
}

// ---- zero accumulators ----
__global__ void k_zero(int n) {
    int stride = gridDim.x * blockDim.x;
    int t = blockIdx.x * blockDim.x + threadIdx.x;
    for (int i = t; i < n * DIM; i += stride) { d_gacc[i] = 0.f; d_sacc[i] = 0.f; }
    for (int i = t; i < n * HEADS; i += stride) d_denom[i] = 0.f;
    for (int i = t; i < n; i += stride) d_deg[i] = 0.f;
}

// ---- detect int64 vs int32 edge_index (odd 32-bit words all zero => int64) ----
__global__ void k_detect(const unsigned* __restrict__ e) {
    if (threadIdx.x == 0 && blockIdx.x == 0) {
        int all0 = 1;
        for (int i = 1; i < 64; i += 2) all0 &= (e[i] == 0u);
        d_is64 = all0;
    }
}

// ---- GEMM1: h = x @ W_gat  (64x128 tile, 256 threads) ----
__global__ void k_gemm_h(const float* __restrict__ x, const float* __restrict__ W, int n) {
    __shared__ float xs[64][16];
    __shared__ float ws[16][128];
    int tid = threadIdx.x, tx = tid & 31, ty = tid >> 5;
    int rowBase = blockIdx.x * 64;
    float acc[8][4];
#pragma unroll
    for (int r = 0; r < 8; r++) { acc[r][0] = acc[r][1] = acc[r][2] = acc[r][3] = 0.f; }
    for (int kk = 0; kk < 8; kk++) {
        int r = tid >> 2, k4 = (tid & 3) << 2;
        int gr = rowBase + r;
        float4 v = make_float4(0.f, 0.f, 0.f, 0.f);
        if (gr < n) v = *(const float4*)&x[(size_t)gr * DIM + kk * 16 + k4];
        *(float4*)&xs[r][k4] = v;
#pragma unroll
        for (int i = 0; i < 2; i++) {
            int id = tid + i * 256;
            int wr = id >> 5, wc = (id & 31) << 2;
            *(float4*)&ws[wr][wc] = *(const float4*)&W[(size_t)(kk * 16 + wr) * DIM + wc];
        }
        __syncthreads();
#pragma unroll
        for (int k = 0; k < 16; k++) {
            float4 b = *(float4*)&ws[k][tx << 2];
#pragma unroll
            for (int r8 = 0; r8 < 8; r8++) {
                float a = xs[ty * 8 + r8][k];
                acc[r8][0] += a * b.x; acc[r8][1] += a * b.y;
                acc[r8][2] += a * b.z; acc[r8][3] += a * b.w;
            }
        }
        __syncthreads();
    }
#pragma unroll
    for (int r8 = 0; r8 < 8; r8++) {
        int gr = rowBase + ty * 8 + r8;
        if (gr < n)
            *(float4*)&d_h[(size_t)gr * DIM + (tx << 2)] =
                make_float4(acc[r8][0], acc[r8][1], acc[r8][2], acc[r8][3]);
    }
}

// ---- attention logits: a_src/a_dst per node (warp per node) ----
__global__ void k_attn(const float* __restrict__ att_src, const float* __restrict__ att_dst, int n) {
    int w = (blockIdx.x * blockDim.x + threadIdx.x) >> 5;
    int lane = threadIdx.x & 31;
    if (w >= n) return;
    int hd = lane >> 3, cin = (lane & 7) << 2;
    float4 hv = *(const float4*)&d_h[(size_t)w * DIM + (lane << 2)];
    float4 s4 = *(const float4*)&att_src[hd * 32 + cin];
    float4 d4 = *(const float4*)&att_dst[hd * 32 + cin];
    float ps = hv.x * s4.x + hv.y * s4.y + hv.z * s4.z + hv.w * s4.w;
    float pd = hv.x * d4.x + hv.y * d4.y + hv.z * d4.z + hv.w * d4.w;
#pragma unroll
    for (int o = 4; o; o >>= 1) {
        ps += __shfl_xor_sync(0xffffffffu, ps, o);
        pd += __shfl_xor_sync(0xffffffffu, pd, o);
    }
    if ((lane & 7) == 0) { d_asrc[w * 4 + hd] = ps; d_adst[w * 4 + hd] = pd; }
}

// ---- precompose weights: B = Wl@Wp2, C = Wr@Wp2 + I, dvec = bl@Wp2 + bp ----
__global__ void k_prep(const float* __restrict__ Wl, const float* __restrict__ Wr,
                       const float* __restrict__ bl, const float* __restrict__ Wp,
                       const float* __restrict__ bp) {
    int nn = threadIdx.x;
    int b = blockIdx.x;
    const float* Wp2 = Wp + DIM * DIM;
    if (b < DIM) {
        float s = 0.f;
        for (int j = 0; j < DIM; j++) s += Wl[b * DIM + j] * Wp2[j * DIM + nn];
        d_B[b * DIM + nn] = s;
    } else if (b < 2 * DIM) {
        int k = b - DIM;
        float s = (k == nn) ? 1.f : 0.f;
        for (int j = 0; j < DIM; j++) s += Wr[k * DIM + j] * Wp2[j * DIM + nn];
        d_C[k * DIM + nn] = s;
    } else {
        float s = bp[nn];
        for (int j = 0; j < DIM; j++) s += bl[j] * Wp2[j * DIM + nn];
        d_dvec[nn] = s;
    }
}

// ---- single edge pass: denom += ex, gacc += h[s]*ex, sacc += x[s], deg += 1 ----
__global__ void k_edge(const int* __restrict__ eidx, const float* __restrict__ x, int E) {
    int is64 = d_is64;
    int w = (blockIdx.x * blockDim.x + threadIdx.x) >> 5;
    int lane = threadIdx.x & 31;
    int nw = (gridDim.x * blockDim.x) >> 5;
    for (int e = w; e < E; e += nw) {
        int s, d;
        if (is64) {
            const long long* p = (const long long*)eidx;
            s = (int)__ldg(&p[e]); d = (int)__ldg(&p[E + e]);
        } else {
            s = __ldg(&eidx[e]); d = __ldg(&eidx[E + e]);
        }
        int hd = lane >> 3;
        float ee = d_asrc[s * 4 + hd] + d_adst[d * 4 + hd];
        ee = ee > 0.f ? ee : 0.2f * ee;
        float ex = __expf(ee);
        if ((lane & 7) == 0) atomicAdd(&d_denom[d * 4 + hd], ex);
        if (lane == 0) atomicAdd(&d_deg[d], 1.0f);
        int c = lane << 2;
        size_t soff = (size_t)s * DIM + c;
        size_t doff = (size_t)d * DIM + c;
        float4 hv = *(const float4*)&d_h[soff];
        float4 xv = __ldg((const float4*)&x[soff]);
        red4(&d_gacc[doff], hv.x * ex, hv.y * ex, hv.z * ex, hv.w * ex);
        red4(&d_sacc[doff], xv.x, xv.y, xv.z, xv.w);
    }
}

// ---- finalize: self loop + normalize (in place), mean (in place) ----
__global__ void k_fin(const float* __restrict__ b_gat, int n) {
    int w = (blockIdx.x * blockDim.x + threadIdx.x) >> 5;
    int lane = threadIdx.x & 31;
    if (w >= n) return;
    int hd = lane >> 3;
    float ee = d_asrc[w * 4 + hd] + d_adst[w * 4 + hd];
    ee = ee > 0.f ? ee : 0.2f * ee;
    float exs = __expf(ee);
    float den = d_denom[w * 4 + hd] + exs + 1e-16f;
    float inv = 1.f / den;
    int c = lane << 2;
    size_t off = (size_t)w * DIM + c;
    float4 g = *(float4*)&d_gacc[off];
    float4 hv = *(const float4*)&d_h[off];
    float4 bg = *(const float4*)&b_gat[c];
    g.x = (g.x + hv.x * exs) * inv + bg.x;
    g.y = (g.y + hv.y * exs) * inv + bg.y;
    g.z = (g.z + hv.z * exs) * inv + bg.z;
    g.w = (g.w + hv.w * exs) * inv + bg.w;
    *(float4*)&d_gacc[off] = g;
    float dg = d_deg[w]; dg = dg < 1.f ? 1.f : dg;
    float idg = 1.f / dg;
    float4 sv = *(float4*)&d_sacc[off];
    sv.x *= idg; sv.y *= idg; sv.z *= idg; sv.w *= idg;
    *(float4*)&d_sacc[off] = sv;
}

// ---- final fused 3-GEMM (K=384) + bias + LayerNorm ----
__global__ void k_final(const float* __restrict__ x, const float* __restrict__ Wp,
                        const float* __restrict__ gamma, const float* __restrict__ beta,
                        float* __restrict__ out, int n) {
    __shared__ float xs[64][16];
    __shared__ float ws[16][128];
    int tid = threadIdx.x, tx = tid & 31, ty = tid >> 5;
    int rowBase = blockIdx.x * 64;
    float acc[8][4];
#pragma unroll
    for (int r = 0; r < 8; r++) { acc[r][0] = acc[r][1] = acc[r][2] = acc[r][3] = 0.f; }
    for (int kk = 0; kk < 24; kk++) {
        int seg = kk >> 3;
        int krel = (kk & 7) * 16;
        const float* src = (seg == 0) ? d_gacc : (seg == 1) ? d_sacc : x;
        const float* wseg = (seg == 0) ? Wp : (seg == 1) ? d_B : d_C;
        int r = tid >> 2, k4 = (tid & 3) << 2;
        int gr = rowBase + r;
        float4 v = make_float4(0.f, 0.f, 0.f, 0.f);
        if (gr < n) v = *(const float4*)&src[(size_t)gr * DIM + krel + k4];
        *(float4*)&xs[r][k4] = v;
#pragma unroll
        for (int i = 0; i < 2; i++) {
            int id = tid + i * 256;
            int wr = id >> 5, wc = (id & 31) << 2;
            *(float4*)&ws[wr][wc] = *(const float4*)&wseg[(size_t)(krel + wr) * DIM + wc];
        }
        __syncthreads();
#pragma unroll
        for (int k = 0; k < 16; k++) {
            float4 b = *(float4*)&ws[k][tx << 2];
#pragma unroll
            for (int r8 = 0; r8 < 8; r8++) {
                float a = xs[ty * 8 + r8][k];
                acc[r8][0] += a * b.x; acc[r8][1] += a * b.y;
                acc[r8][2] += a * b.z; acc[r8][3] += a * b.w;
            }
        }
        __syncthreads();
    }
    // epilogue: + dvec, LayerNorm per row (warp owns rows fully: lanes tx cover 128 cols)
    float4 dv = *(const float4*)&d_dvec[tx << 2];
    float4 gm = *(const float4*)&gamma[tx << 2];
    float4 bt = *(const float4*)&beta[tx << 2];
#pragma unroll
    for (int r8 = 0; r8 < 8; r8++) {
        float v0 = acc[r8][0] + dv.x, v1 = acc[r8][1] + dv.y;
        float v2 = acc[r8][2] + dv.z, v3 = acc[r8][3] + dv.w;
        float sum = v0 + v1 + v2 + v3;
        float sq = v0 * v0 + v1 * v1 + v2 * v2 + v3 * v3;
#pragma unroll
        for (int o = 16; o; o >>= 1) {
            sum += __shfl_xor_sync(0xffffffffu, sum, o);
            sq  += __shfl_xor_sync(0xffffffffu, sq, o);
        }
        float mu = sum * (1.f / 128.f);
        float var = sq * (1.f / 128.f) - mu * mu;
        float rstd = rsqrtf(var + 1e-5f);
        int gr = rowBase + ty * 8 + r8;
        if (gr < n) {
            float4 o4;
            o4.x = (v0 - mu) * rstd * gm.x + bt.x;
            o4.y = (v1 - mu) * rstd * gm.y + bt.y;
            o4.z = (v2 - mu) * rstd * gm.z + bt.z;
            o4.w = (v3 - mu) * rstd * gm.w + bt.w;
            *(float4*)&out[(size_t)gr * DIM + (tx << 2)] = o4;
        }
    }
}

extern "C" void kernel_launch(void* const* d_in, const int* in_sizes, int n_in,
                              void* d_out, int out_size) {
    const float* x       = (const float*)d_in[0];
    const void*  eidx    = d_in[1];
    const float* W_gat   = (const float*)d_in[2];
    const float* att_src = (const float*)d_in[3];
    const float* att_dst = (const float*)d_in[4];
    const float* b_gat   = (const float*)d_in[5];
    const float* W_l     = (const float*)d_in[6];
    const float* b_l     = (const float*)d_in[7];
    const float* W_r     = (const float*)d_in[8];
    const float* W_proj  = (const float*)d_in[9];
    const float* b_proj  = (const float*)d_in[10];
    const float* gamma   = (const float*)d_in[11];
    const float* beta    = (const float*)d_in[12];

    int n = in_sizes[0] / DIM;
    int E = in_sizes[1] / 2;

    k_zero<<<1024, 256>>>(n);
    k_gemm_h<<<(n + 63) / 64, 256>>>(x, W_gat, n);
    k_attn<<<(n * 32 + 255) / 256, 256>>>(att_src, att_dst, n);
    k_prep<<<257, 128>>>(W_l, W_r, b_l, W_proj, b_proj);
    k_detect<<<1, 32>>>((const unsigned*)eidx);
    k_edge<<<(E + 7) / 8, 256>>>((const int*)eidx, x, E);
    k_fin<<<(n * 32 + 255) / 256, 256>>>(b_gat, n);
    k_final<<<(n + 63) / 64, 256>>>(x, W_proj, gamma, beta, (float*)d_out, n);
}

// round 2
// speedup vs baseline: 1.3948x; 1.3948x over previous
#include <cuda_runtime.h>
#include <cuda_bf16.h>

#define DIM 128
#define HEADS 4
#define NMAX 50000
#define BCAP 64
#define OVF_CAP 2048

// ---- device scratch (static; no allocations) ----
__device__ float d_h[NMAX * DIM];        // x @ W_gat
__device__ float d_asrc[NMAX * HEADS];
__device__ float d_adst[NMAX * HEADS];
__device__ float d_gacc[NMAX * DIM];     // gat_out (written once by gather)
__device__ float d_sacc[NMAX * DIM];     // SAGE mean (written once by gather)
__device__ float d_B[DIM * DIM];         // W_sage_l @ Wp2
__device__ float d_C[DIM * DIM];         // W_sage_r @ Wp2 + I
__device__ float d_dvec[DIM];            // b_sage_l @ Wp2 + b_proj
__device__ int   d_fill[NMAX];           // per-dst edge counts (atomic)
__device__ int   d_esrc[NMAX * BCAP];    // bucketed src ids per dst
__device__ int   d_ovf[OVF_CAP * 2];     // overflow (s,d) pairs
__device__ int   d_ovf_cnt;
__device__ int   d_is64;

// ---- detect int64 vs int32 edge_index (odd 32-bit words all zero => int64) ----
__global__ void k_detect(const unsigned* __restrict__ e) {
    if (threadIdx.x == 0 && blockIdx.x == 0) {
        int all0 = 1;
        for (int i = 1; i < 64; i += 2) all0 &= (e[i] == 0u);
        d_is64 = all0;
    }
}

// ---- zero fill counters + overflow counter ----
__global__ void k_zero_fill(int n) {
    int t = blockIdx.x * blockDim.x + threadIdx.x;
    if (t < n) d_fill[t] = 0;
    if (t == 0) d_ovf_cnt = 0;
}

// ---- GEMM1: h = x @ W_gat  (64x128 tile, 256 threads) ----
__global__ void k_gemm_h(const float* __restrict__ x, const float* __restrict__ W, int n) {
    __shared__ float xs[64][16];
    __shared__ float ws[16][128];
    int tid = threadIdx.x, tx = tid & 31, ty = tid >> 5;
    int rowBase = blockIdx.x * 64;
    float acc[8][4];
#pragma unroll
    for (int r = 0; r < 8; r++) { acc[r][0] = acc[r][1] = acc[r][2] = acc[r][3] = 0.f; }
    for (int kk = 0; kk < 8; kk++) {
        int r = tid >> 2, k4 = (tid & 3) << 2;
        int gr = rowBase + r;
        float4 v = make_float4(0.f, 0.f, 0.f, 0.f);
        if (gr < n) v = *(const float4*)&x[(size_t)gr * DIM + kk * 16 + k4];
        *(float4*)&xs[r][k4] = v;
#pragma unroll
        for (int i = 0; i < 2; i++) {
            int id = tid + i * 256;
            int wr = id >> 5, wc = (id & 31) << 2;
            *(float4*)&ws[wr][wc] = *(const float4*)&W[(size_t)(kk * 16 + wr) * DIM + wc];
        }
        __syncthreads();
#pragma unroll
        for (int k = 0; k < 16; k++) {
            float4 b = *(float4*)&ws[k][tx << 2];
#pragma unroll
            for (int r8 = 0; r8 < 8; r8++) {
                float a = xs[ty * 8 + r8][k];
                acc[r8][0] += a * b.x; acc[r8][1] += a * b.y;
                acc[r8][2] += a * b.z; acc[r8][3] += a * b.w;
            }
        }
        __syncthreads();
    }
#pragma unroll
    for (int r8 = 0; r8 < 8; r8++) {
        int gr = rowBase + ty * 8 + r8;
        if (gr < n)
            *(float4*)&d_h[(size_t)gr * DIM + (tx << 2)] =
                make_float4(acc[r8][0], acc[r8][1], acc[r8][2], acc[r8][3]);
    }
}

// ---- scatter edges into per-dst buckets ----
__global__ void k_scatter(const int* __restrict__ eidx, int E) {
    int is64 = d_is64;
    int e = blockIdx.x * blockDim.x + threadIdx.x;
    if (e >= E) return;
    int s, d;
    if (is64) {
        const long long* p = (const long long*)eidx;
        s = (int)__ldg(&p[e]); d = (int)__ldg(&p[E + e]);
    } else {
        s = __ldg(&eidx[e]); d = __ldg(&eidx[E + e]);
    }
    int slot = atomicAdd(&d_fill[d], 1);
    if (slot < BCAP) {
        d_esrc[d * BCAP + slot] = s;
    } else {
        int o = atomicAdd(&d_ovf_cnt, 1);
        if (o < OVF_CAP) { d_ovf[2 * o] = s; d_ovf[2 * o + 1] = d; }
    }
}

// ---- attention logits: a_src/a_dst per node (warp per node) ----
__global__ void k_attn(const float* __restrict__ att_src, const float* __restrict__ att_dst, int n) {
    int w = (blockIdx.x * blockDim.x + threadIdx.x) >> 5;
    int lane = threadIdx.x & 31;
    if (w >= n) return;
    int hd = lane >> 3, cin = (lane & 7) << 2;
    float4 hv = *(const float4*)&d_h[(size_t)w * DIM + (lane << 2)];
    float4 s4 = *(const float4*)&att_src[hd * 32 + cin];
    float4 d4 = *(const float4*)&att_dst[hd * 32 + cin];
    float ps = hv.x * s4.x + hv.y * s4.y + hv.z * s4.z + hv.w * s4.w;
    float pd = hv.x * d4.x + hv.y * d4.y + hv.z * d4.z + hv.w * d4.w;
#pragma unroll
    for (int o = 4; o; o >>= 1) {
        ps += __shfl_xor_sync(0xffffffffu, ps, o);
        pd += __shfl_xor_sync(0xffffffffu, pd, o);
    }
    if ((lane & 7) == 0) { d_asrc[w * 4 + hd] = ps; d_adst[w * 4 + hd] = pd; }
}

// ---- gather: warp per dst node. GAT softmax-accum + SAGE sum in registers,
//      fused self-loop, normalization, bias. Writes each row exactly once. ----
__global__ void k_gather(const float* __restrict__ x, const float* __restrict__ b_gat, int n) {
    int w = (blockIdx.x * blockDim.x + threadIdx.x) >> 5;
    int lane = threadIdx.x & 31;
    if (w >= n) return;
    int hd = lane >> 3;
    int c = lane << 2;
    int fill = d_fill[w];
    int deg = fill < BCAP ? fill : BCAP;
    float adst = d_adst[w * 4 + hd];
    float4 g = make_float4(0.f, 0.f, 0.f, 0.f);
    float4 sa = make_float4(0.f, 0.f, 0.f, 0.f);
    float den = 0.f;

    for (int base = 0; base < deg; base += 32) {
        int cnt = deg - base; if (cnt > 32) cnt = 32;
        int myS = (lane < cnt) ? d_esrc[w * BCAP + base + lane] : 0;
#pragma unroll 4
        for (int j = 0; j < cnt; j++) {
            int s = __shfl_sync(0xffffffffu, myS, j);
            float asr = __ldg(&d_asrc[s * 4 + hd]);
            float ee = asr + adst;
            ee = ee > 0.f ? ee : 0.2f * ee;
            float ex = __expf(ee);
            den += ex;
            float4 hv = *(const float4*)&d_h[(size_t)s * DIM + c];
            float4 xv = __ldg((const float4*)&x[(size_t)s * DIM + c]);
            g.x += hv.x * ex; g.y += hv.y * ex; g.z += hv.z * ex; g.w += hv.w * ex;
            sa.x += xv.x; sa.y += xv.y; sa.z += xv.z; sa.w += xv.w;
        }
    }

    // overflow edges (normally zero)
    int oc = d_ovf_cnt;
    if (oc > 0) {
        if (oc > OVF_CAP) oc = OVF_CAP;
        for (int k = 0; k < oc; k++) {
            if (d_ovf[2 * k + 1] == w) {
                int s = d_ovf[2 * k];
                float asr = __ldg(&d_asrc[s * 4 + hd]);
                float ee = asr + adst;
                ee = ee > 0.f ? ee : 0.2f * ee;
                float ex = __expf(ee);
                den += ex;
                float4 hv = *(const float4*)&d_h[(size_t)s * DIM + c];
                float4 xv = __ldg((const float4*)&x[(size_t)s * DIM + c]);
                g.x += hv.x * ex; g.y += hv.y * ex; g.z += hv.z * ex; g.w += hv.w * ex;
                sa.x += xv.x; sa.y += xv.y; sa.z += xv.z; sa.w += xv.w;
            }
        }
    }

    // self-loop (GAT only)
    {
        float asr = d_asrc[w * 4 + hd];
        float ee = asr + adst;
        ee = ee > 0.f ? ee : 0.2f * ee;
        float exs = __expf(ee);
        den += exs;
        float4 hv = *(const float4*)&d_h[(size_t)w * DIM + c];
        g.x += hv.x * exs; g.y += hv.y * exs; g.z += hv.z * exs; g.w += hv.w * exs;
    }

    float inv = 1.f / (den + 1e-16f);
    float4 bg = *(const float4*)&b_gat[c];
    size_t off = (size_t)w * DIM + c;
    *(float4*)&d_gacc[off] = make_float4(g.x * inv + bg.x, g.y * inv + bg.y,
                                         g.z * inv + bg.z, g.w * inv + bg.w);
    float dg = fill > 0 ? (float)fill : 1.f;
    float idg = 1.f / dg;
    *(float4*)&d_sacc[off] = make_float4(sa.x * idg, sa.y * idg, sa.z * idg, sa.w * idg);
}

// ---- precompose weights (tiled): B = Wl@Wp2, C = Wr@Wp2 + I, dvec = bl@Wp2 + bp ----
__global__ void k_prep(const float* __restrict__ Wl, const float* __restrict__ Wr,
                       const float* __restrict__ bl, const float* __restrict__ Wp,
                       const float* __restrict__ bp) {
    const float* Wp2 = Wp + DIM * DIM;
    if (blockIdx.x == 4) {  // dvec
        int nn = threadIdx.x;
        if (nn < DIM) {
            float s = bp[nn];
            for (int j = 0; j < DIM; j++) s += bl[j] * Wp2[j * DIM + nn];
            d_dvec[nn] = s;
        }
        return;
    }
    __shared__ float xs[64][16];
    __shared__ float ws[16][128];
    int tid = threadIdx.x, tx = tid & 31, ty = tid >> 5;
    int rowBase = blockIdx.x * 64;            // virtual rows 0..255
    const float* A = (rowBase < 128) ? Wl : Wr;
    int aBase = (rowBase < 128) ? rowBase : rowBase - 128;
    float acc[8][4];
#pragma unroll
    for (int r = 0; r < 8; r++) { acc[r][0] = acc[r][1] = acc[r][2] = acc[r][3] = 0.f; }
    for (int kk = 0; kk < 8; kk++) {
        int r = tid >> 2, k4 = (tid & 3) << 2;
        *(float4*)&xs[r][k4] = *(const float4*)&A[(size_t)(aBase + r) * DIM + kk * 16 + k4];
#pragma unroll
        for (int i = 0; i < 2; i++) {
            int id = tid + i * 256;
            int wr = id >> 5, wc = (id & 31) << 2;
            *(float4*)&ws[wr][wc] = *(const float4*)&Wp2[(size_t)(kk * 16 + wr) * DIM + wc];
        }
        __syncthreads();
#pragma unroll
        for (int k = 0; k < 16; k++) {
            float4 b = *(float4*)&ws[k][tx << 2];
#pragma unroll
            for (int r8 = 0; r8 < 8; r8++) {
                float a = xs[ty * 8 + r8][k];
                acc[r8][0] += a * b.x; acc[r8][1] += a * b.y;
                acc[r8][2] += a * b.z; acc[r8][3] += a * b.w;
            }
        }
        __syncthreads();
    }
#pragma unroll
    for (int r8 = 0; r8 < 8; r8++) {
        int vr = rowBase + ty * 8 + r8;
        int col = tx << 2;
        if (vr < 128) {
            *(float4*)&d_B[vr * DIM + col] =
                make_float4(acc[r8][0], acc[r8][1], acc[r8][2], acc[r8][3]);
        } else {
            int rr = vr - 128;
            float4 v = make_float4(acc[r8][0], acc[r8][1], acc[r8][2], acc[r8][3]);
            if (rr >= col && rr < col + 4) {
                if (rr == col) v.x += 1.f;
                else if (rr == col + 1) v.y += 1.f;
                else if (rr == col + 2) v.z += 1.f;
                else v.w += 1.f;
            }
            *(float4*)&d_C[rr * DIM + col] = v;
        }
    }
}

// ---- final fused 3-GEMM (K=384) + bias + LayerNorm ----
__global__ void k_final(const float* __restrict__ x, const float* __restrict__ Wp,
                        const float* __restrict__ gamma, const float* __restrict__ beta,
                        float* __restrict__ out, int n) {
    __shared__ float xs[64][16];
    __shared__ float ws[16][128];
    int tid = threadIdx.x, tx = tid & 31, ty = tid >> 5;
    int rowBase = blockIdx.x * 64;
    float acc[8][4];
#pragma unroll
    for (int r = 0; r < 8; r++) { acc[r][0] = acc[r][1] = acc[r][2] = acc[r][3] = 0.f; }
    for (int kk = 0; kk < 24; kk++) {
        int seg = kk >> 3;
        int krel = (kk & 7) * 16;
        const float* src = (seg == 0) ? d_gacc : (seg == 1) ? d_sacc : x;
        const float* wseg = (seg == 0) ? Wp : (seg == 1) ? d_B : d_C;
        int r = tid >> 2, k4 = (tid & 3) << 2;
        int gr = rowBase + r;
        float4 v = make_float4(0.f, 0.f, 0.f, 0.f);
        if (gr < n) v = *(const float4*)&src[(size_t)gr * DIM + krel + k4];
        *(float4*)&xs[r][k4] = v;
#pragma unroll
        for (int i = 0; i < 2; i++) {
            int id = tid + i * 256;
            int wr = id >> 5, wc = (id & 31) << 2;
            *(float4*)&ws[wr][wc] = *(const float4*)&wseg[(size_t)(krel + wr) * DIM + wc];
        }
        __syncthreads();
#pragma unroll
        for (int k = 0; k < 16; k++) {
            float4 b = *(float4*)&ws[k][tx << 2];
#pragma unroll
            for (int r8 = 0; r8 < 8; r8++) {
                float a = xs[ty * 8 + r8][k];
                acc[r8][0] += a * b.x; acc[r8][1] += a * b.y;
                acc[r8][2] += a * b.z; acc[r8][3] += a * b.w;
            }
        }
        __syncthreads();
    }
    float4 dv = *(const float4*)&d_dvec[tx << 2];
    float4 gm = *(const float4*)&gamma[tx << 2];
    float4 bt = *(const float4*)&beta[tx << 2];
#pragma unroll
    for (int r8 = 0; r8 < 8; r8++) {
        float v0 = acc[r8][0] + dv.x, v1 = acc[r8][1] + dv.y;
        float v2 = acc[r8][2] + dv.z, v3 = acc[r8][3] + dv.w;
        float sum = v0 + v1 + v2 + v3;
        float sq = v0 * v0 + v1 * v1 + v2 * v2 + v3 * v3;
#pragma unroll
        for (int o = 16; o; o >>= 1) {
            sum += __shfl_xor_sync(0xffffffffu, sum, o);
            sq  += __shfl_xor_sync(0xffffffffu, sq, o);
        }
        float mu = sum * (1.f / 128.f);
        float var = sq * (1.f / 128.f) - mu * mu;
        float rstd = rsqrtf(var + 1e-5f);
        int gr = rowBase + ty * 8 + r8;
        if (gr < n) {
            float4 o4;
            o4.x = (v0 - mu) * rstd * gm.x + bt.x;
            o4.y = (v1 - mu) * rstd * gm.y + bt.y;
            o4.z = (v2 - mu) * rstd * gm.z + bt.z;
            o4.w = (v3 - mu) * rstd * gm.w + bt.w;
            *(float4*)&out[(size_t)gr * DIM + (tx << 2)] = o4;
        }
    }
}

extern "C" void kernel_launch(void* const* d_in, const int* in_sizes, int n_in,
                              void* d_out, int out_size) {
    const float* x       = (const float*)d_in[0];
    const void*  eidx    = d_in[1];
    const float* W_gat   = (const float*)d_in[2];
    const float* att_src = (const float*)d_in[3];
    const float* att_dst = (const float*)d_in[4];
    const float* b_gat   = (const float*)d_in[5];
    const float* W_l     = (const float*)d_in[6];
    const float* b_l     = (const float*)d_in[7];
    const float* W_r     = (const float*)d_in[8];
    const float* W_proj  = (const float*)d_in[9];
    const float* b_proj  = (const float*)d_in[10];
    const float* gamma   = (const float*)d_in[11];
    const float* beta    = (const float*)d_in[12];

    int n = in_sizes[0] / DIM;
    int E = in_sizes[1] / 2;

    k_detect<<<1, 32>>>((const unsigned*)eidx);                    // 1
    k_zero_fill<<<(n + 255) / 256, 256>>>(n);                      // 2
    k_gemm_h<<<(n + 63) / 64, 256>>>(x, W_gat, n);                 // 3
    k_scatter<<<(E + 255) / 256, 256>>>((const int*)eidx, E);      // 4
    k_attn<<<(n * 32 + 255) / 256, 256>>>(att_src, att_dst, n);    // 5
    k_gather<<<(n * 32 + 255) / 256, 256>>>(x, b_gat, n);          // 6 <- ncu -s 5 capture
    k_prep<<<5, 256>>>(W_l, W_r, b_l, W_proj, b_proj);             // 7
    k_final<<<(n + 63) / 64, 256>>>(x, W_proj, gamma, beta, (float*)d_out, n);  // 8
}

// round 3
// speedup vs baseline: 2.1654x; 1.5525x over previous
#include <cuda_runtime.h>
#include <cuda_fp16.h>

#define DIM 128
#define HEADS 4
#define NMAX 50000
#define BCAP 64
#define OVF_CAP 2048

// ---- device scratch (static; no allocations) ----
__device__ __half d_h16[NMAX * DIM];     // x @ W_gat, fp16
__device__ __half d_x16[NMAX * DIM];     // x, fp16
__device__ float d_asrc[NMAX * HEADS];
__device__ float d_adst[NMAX * HEADS];
__device__ float d_gacc[NMAX * DIM];     // gat_out
__device__ float d_sacc[NMAX * DIM];     // SAGE mean
__device__ float d_B[DIM * DIM];         // W_sage_l @ Wp2
__device__ float d_C[DIM * DIM];         // W_sage_r @ Wp2 + I
__device__ float d_dvec[DIM];            // b_sage_l @ Wp2 + b_proj
__device__ int   d_fill[NMAX];
__device__ int   d_esrc[NMAX * BCAP];
__device__ int   d_ovf[OVF_CAP * 2];
__device__ int   d_ovf_cnt;
__device__ int   d_is64;

// ---- tf32 helpers ----
__device__ __forceinline__ float f2tf(float f) {
    unsigned u; asm("cvt.rna.tf32.f32 %0, %1;" : "=r"(u) : "f"(f));
    return __uint_as_float(u);
}
__device__ __forceinline__ void mma_tf32(float c[4], unsigned a0, unsigned a1,
                                         unsigned a2, unsigned a3,
                                         unsigned b0, unsigned b1) {
    asm volatile(
        "mma.sync.aligned.m16n8k8.row.col.f32.tf32.tf32.f32 "
        "{%0,%1,%2,%3}, {%4,%5,%6,%7}, {%8,%9}, {%0,%1,%2,%3};"
        : "+f"(c[0]), "+f"(c[1]), "+f"(c[2]), "+f"(c[3])
        : "r"(a0), "r"(a1), "r"(a2), "r"(a3), "r"(b0), "r"(b1));
}

struct SmemGemm { float xs[64][20]; float ws[16][136]; };

// ---- detect int64 vs int32 edge_index ----
__global__ void k_detect(const unsigned* __restrict__ e) {
    if (threadIdx.x == 0 && blockIdx.x == 0) {
        int all0 = 1;
        for (int i = 1; i < 64; i += 2) all0 &= (e[i] == 0u);
        d_is64 = all0;
    }
}

// ---- zero fill counters ----
__global__ void k_zero_fill(int n) {
    int t = blockIdx.x * blockDim.x + threadIdx.x;
    if (t < n) d_fill[t] = 0;
    if (t == 0) d_ovf_cnt = 0;
}

// ---- GEMM1 (tf32 mma): h = x @ W_gat, fused attn logits + fp16 h store ----
__global__ void k_gemm_h(const float* __restrict__ x, const float* __restrict__ W,
                         const float* __restrict__ att_src, const float* __restrict__ att_dst,
                         int n) {
    __shared__ union USm { SmemGemm s; float ot[64][132]; } u;
    int tid = threadIdx.x, lane = tid & 31, wid = tid >> 5;
    int rowBase = blockIdx.x * 64;
    int warpM = wid & 3, warpN = wid >> 2;
    int g = lane >> 2, tig = lane & 3;
    float c[8][4];
#pragma unroll
    for (int i = 0; i < 8; i++) { c[i][0] = c[i][1] = c[i][2] = c[i][3] = 0.f; }

    for (int kk = 0; kk < 8; kk++) {
        int r = tid >> 2, k4 = (tid & 3) << 2;
        int gr = rowBase + r;
        float4 v = make_float4(0.f, 0.f, 0.f, 0.f);
        if (gr < n) v = *(const float4*)&x[(size_t)gr * DIM + kk * 16 + k4];
        u.s.xs[r][k4 + 0] = f2tf(v.x); u.s.xs[r][k4 + 1] = f2tf(v.y);
        u.s.xs[r][k4 + 2] = f2tf(v.z); u.s.xs[r][k4 + 3] = f2tf(v.w);
#pragma unroll
        for (int i = 0; i < 2; i++) {
            int id = tid + i * 256;
            int wr = id >> 5, wc = (id & 31) << 2;
            float4 w4 = *(const float4*)&W[(size_t)(kk * 16 + wr) * DIM + wc];
            u.s.ws[wr][wc + 0] = f2tf(w4.x); u.s.ws[wr][wc + 1] = f2tf(w4.y);
            u.s.ws[wr][wc + 2] = f2tf(w4.z); u.s.ws[wr][wc + 3] = f2tf(w4.w);
        }
        __syncthreads();
#pragma unroll
        for (int k8 = 0; k8 < 16; k8 += 8) {
            unsigned a0 = __float_as_uint(u.s.xs[warpM * 16 + g][k8 + tig]);
            unsigned a1 = __float_as_uint(u.s.xs[warpM * 16 + g + 8][k8 + tig]);
            unsigned a2 = __float_as_uint(u.s.xs[warpM * 16 + g][k8 + tig + 4]);
            unsigned a3 = __float_as_uint(u.s.xs[warpM * 16 + g + 8][k8 + tig + 4]);
#pragma unroll
            for (int n8 = 0; n8 < 8; n8++) {
                int cb = warpN * 64 + n8 * 8 + g;
                unsigned b0 = __float_as_uint(u.s.ws[k8 + tig][cb]);
                unsigned b1 = __float_as_uint(u.s.ws[k8 + tig + 4][cb]);
                mma_tf32(c[n8], a0, a1, a2, a3, b0, b1);
            }
        }
        __syncthreads();
    }
    // dump C frags to smem tile
    {
        int rb = warpM * 16, cb = warpN * 64;
#pragma unroll
        for (int n8 = 0; n8 < 8; n8++) {
            int cc = cb + n8 * 8 + 2 * tig;
            u.ot[rb + g][cc] = c[n8][0];     u.ot[rb + g][cc + 1] = c[n8][1];
            u.ot[rb + g + 8][cc] = c[n8][2]; u.ot[rb + g + 8][cc + 1] = c[n8][3];
        }
    }
    __syncthreads();
    // epilogue: fp16 h store + attention logits
    int tx = lane, ty = wid;
    float4 as4 = *(const float4*)&att_src[tx << 2];
    float4 ad4 = *(const float4*)&att_dst[tx << 2];
#pragma unroll
    for (int r8 = 0; r8 < 8; r8++) {
        int gr = rowBase + ty * 8 + r8;
        float4 hv = *(float4*)&u.ot[ty * 8 + r8][tx << 2];
        if (gr < n) {
            __half2 p0 = __floats2half2_rn(hv.x, hv.y);
            __half2 p1 = __floats2half2_rn(hv.z, hv.w);
            uint2 q;
            q.x = *(unsigned*)&p0; q.y = *(unsigned*)&p1;
            *(uint2*)&d_h16[(size_t)gr * DIM + (tx << 2)] = q;
        }
        float ps = hv.x * as4.x + hv.y * as4.y + hv.z * as4.z + hv.w * as4.w;
        float pd = hv.x * ad4.x + hv.y * ad4.y + hv.z * ad4.z + hv.w * ad4.w;
#pragma unroll
        for (int o = 4; o; o >>= 1) {
            ps += __shfl_xor_sync(0xffffffffu, ps, o);
            pd += __shfl_xor_sync(0xffffffffu, pd, o);
        }
        if ((tx & 7) == 0 && gr < n) {
            int hd = tx >> 3;
            d_asrc[gr * 4 + hd] = ps;
            d_adst[gr * 4 + hd] = pd;
        }
    }
}

// ---- scatter edges into per-dst buckets ----
__global__ void k_scatter(const int* __restrict__ eidx, int E) {
    int is64 = d_is64;
    int e = blockIdx.x * blockDim.x + threadIdx.x;
    if (e >= E) return;
    int s, d;
    if (is64) {
        const long long* p = (const long long*)eidx;
        s = (int)__ldg(&p[e]); d = (int)__ldg(&p[E + e]);
    } else {
        s = __ldg(&eidx[e]); d = __ldg(&eidx[E + e]);
    }
    int slot = atomicAdd(&d_fill[d], 1);
    if (slot < BCAP) {
        d_esrc[d * BCAP + slot] = s;
    } else {
        int o = atomicAdd(&d_ovf_cnt, 1);
        if (o < OVF_CAP) { d_ovf[2 * o] = s; d_ovf[2 * o + 1] = d; }
    }
}

// ---- convert x to fp16 ----
__global__ void k_xcvt(const float* __restrict__ x, int n) {
    int t = blockIdx.x * blockDim.x + threadIdx.x;
    int total = n * (DIM / 4);
    if (t >= total) return;
    float4 v = __ldg((const float4*)x + t);
    __half2 p0 = __floats2half2_rn(v.x, v.y);
    __half2 p1 = __floats2half2_rn(v.z, v.w);
    uint2 q; q.x = *(unsigned*)&p0; q.y = *(unsigned*)&p1;
    *(uint2*)&d_x16[(size_t)t * 4] = q;
}

// ---- gather: warp per dst node, fp16 payload, register accumulation ----
__global__ void k_gather(const float* __restrict__ b_gat, int n) {
    int w = (blockIdx.x * blockDim.x + threadIdx.x) >> 5;
    int lane = threadIdx.x & 31;
    if (w >= n) return;
    int hd = lane >> 3;
    int c = lane << 2;
    int fill = d_fill[w];
    int deg = fill < BCAP ? fill : BCAP;
    float adst = d_adst[w * 4 + hd];
    float4 g = make_float4(0.f, 0.f, 0.f, 0.f);
    float4 sa = make_float4(0.f, 0.f, 0.f, 0.f);
    float den = 0.f;

    for (int base = 0; base < deg; base += 32) {
        int cnt = deg - base; if (cnt > 32) cnt = 32;
        int myS = (lane < cnt) ? d_esrc[w * BCAP + base + lane] : 0;
#pragma unroll 4
        for (int j = 0; j < cnt; j++) {
            int s = __shfl_sync(0xffffffffu, myS, j);
            float asr = __ldg(&d_asrc[s * 4 + hd]);
            float ee = asr + adst;
            ee = ee > 0.f ? ee : 0.2f * ee;
            float ex = __expf(ee);
            den += ex;
            uint2 hraw = __ldg((const uint2*)&d_h16[(size_t)s * DIM + c]);
            uint2 xraw = __ldg((const uint2*)&d_x16[(size_t)s * DIM + c]);
            float2 h01 = __half22float2(*(__half2*)&hraw.x);
            float2 h23 = __half22float2(*(__half2*)&hraw.y);
            float2 x01 = __half22float2(*(__half2*)&xraw.x);
            float2 x23 = __half22float2(*(__half2*)&xraw.y);
            g.x += h01.x * ex; g.y += h01.y * ex; g.z += h23.x * ex; g.w += h23.y * ex;
            sa.x += x01.x; sa.y += x01.y; sa.z += x23.x; sa.w += x23.y;
        }
    }

    // overflow edges (normally zero)
    int oc = d_ovf_cnt;
    if (oc > 0) {
        if (oc > OVF_CAP) oc = OVF_CAP;
        for (int k = 0; k < oc; k++) {
            if (d_ovf[2 * k + 1] == w) {
                int s = d_ovf[2 * k];
                float asr = __ldg(&d_asrc[s * 4 + hd]);
                float ee = asr + adst;
                ee = ee > 0.f ? ee : 0.2f * ee;
                float ex = __expf(ee);
                den += ex;
                uint2 hraw = __ldg((const uint2*)&d_h16[(size_t)s * DIM + c]);
                uint2 xraw = __ldg((const uint2*)&d_x16[(size_t)s * DIM + c]);
                float2 h01 = __half22float2(*(__half2*)&hraw.x);
                float2 h23 = __half22float2(*(__half2*)&hraw.y);
                float2 x01 = __half22float2(*(__half2*)&xraw.x);
                float2 x23 = __half22float2(*(__half2*)&xraw.y);
                g.x += h01.x * ex; g.y += h01.y * ex; g.z += h23.x * ex; g.w += h23.y * ex;
                sa.x += x01.x; sa.y += x01.y; sa.z += x23.x; sa.w += x23.y;
            }
        }
    }

    // self-loop (GAT only)
    {
        float asr = d_asrc[w * 4 + hd];
        float ee = asr + adst;
        ee = ee > 0.f ? ee : 0.2f * ee;
        float exs = __expf(ee);
        den += exs;
        uint2 hraw = *(const uint2*)&d_h16[(size_t)w * DIM + c];
        float2 h01 = __half22float2(*(__half2*)&hraw.x);
        float2 h23 = __half22float2(*(__half2*)&hraw.y);
        g.x += h01.x * exs; g.y += h01.y * exs; g.z += h23.x * exs; g.w += h23.y * exs;
    }

    float inv = 1.f / (den + 1e-16f);
    float4 bg = *(const float4*)&b_gat[c];
    size_t off = (size_t)w * DIM + c;
    *(float4*)&d_gacc[off] = make_float4(g.x * inv + bg.x, g.y * inv + bg.y,
                                         g.z * inv + bg.z, g.w * inv + bg.w);
    float dg = fill > 0 ? (float)fill : 1.f;
    float idg = 1.f / dg;
    *(float4*)&d_sacc[off] = make_float4(sa.x * idg, sa.y * idg, sa.z * idg, sa.w * idg);
}

// ---- precompose weights: B = Wl@Wp2, C = Wr@Wp2 + I, dvec = bl@Wp2 + bp ----
__global__ void k_prep(const float* __restrict__ Wl, const float* __restrict__ Wr,
                       const float* __restrict__ bl, const float* __restrict__ Wp,
                       const float* __restrict__ bp) {
    const float* Wp2 = Wp + DIM * DIM;
    if (blockIdx.x == 4) {
        int nn = threadIdx.x;
        if (nn < DIM) {
            float s = bp[nn];
            for (int j = 0; j < DIM; j++) s += bl[j] * Wp2[j * DIM + nn];
            d_dvec[nn] = s;
        }
        return;
    }
    __shared__ float xs[64][16];
    __shared__ float ws[16][128];
    int tid = threadIdx.x, tx = tid & 31, ty = tid >> 5;
    int rowBase = blockIdx.x * 64;
    const float* A = (rowBase < 128) ? Wl : Wr;
    int aBase = (rowBase < 128) ? rowBase : rowBase - 128;
    float acc[8][4];
#pragma unroll
    for (int r = 0; r < 8; r++) { acc[r][0] = acc[r][1] = acc[r][2] = acc[r][3] = 0.f; }
    for (int kk = 0; kk < 8; kk++) {
        int r = tid >> 2, k4 = (tid & 3) << 2;
        *(float4*)&xs[r][k4] = *(const float4*)&A[(size_t)(aBase + r) * DIM + kk * 16 + k4];
#pragma unroll
        for (int i = 0; i < 2; i++) {
            int id = tid + i * 256;
            int wr = id >> 5, wc = (id & 31) << 2;
            *(float4*)&ws[wr][wc] = *(const float4*)&Wp2[(size_t)(kk * 16 + wr) * DIM + wc];
        }
        __syncthreads();
#pragma unroll
        for (int k = 0; k < 16; k++) {
            float4 b = *(float4*)&ws[k][tx << 2];
#pragma unroll
            for (int r8 = 0; r8 < 8; r8++) {
                float a = xs[ty * 8 + r8][k];
                acc[r8][0] += a * b.x; acc[r8][1] += a * b.y;
                acc[r8][2] += a * b.z; acc[r8][3] += a * b.w;
            }
        }
        __syncthreads();
    }
#pragma unroll
    for (int r8 = 0; r8 < 8; r8++) {
        int vr = rowBase + ty * 8 + r8;
        int col = tx << 2;
        if (vr < 128) {
            *(float4*)&d_B[vr * DIM + col] =
                make_float4(acc[r8][0], acc[r8][1], acc[r8][2], acc[r8][3]);
        } else {
            int rr = vr - 128;
            float4 v = make_float4(acc[r8][0], acc[r8][1], acc[r8][2], acc[r8][3]);
            if (rr >= col && rr < col + 4) {
                if (rr == col) v.x += 1.f;
                else if (rr == col + 1) v.y += 1.f;
                else if (rr == col + 2) v.z += 1.f;
                else v.w += 1.f;
            }
            *(float4*)&d_C[rr * DIM + col] = v;
        }
    }
}

// ---- final fused 3-GEMM (tf32 mma, K=384) + bias + LayerNorm ----
__global__ void k_final(const float* __restrict__ x, const float* __restrict__ Wp,
                        const float* __restrict__ gamma, const float* __restrict__ beta,
                        float* __restrict__ out, int n) {
    __shared__ union USm2 { SmemGemm s; float ot[64][132]; } u;
    int tid = threadIdx.x, lane = tid & 31, wid = tid >> 5;
    int rowBase = blockIdx.x * 64;
    int warpM = wid & 3, warpN = wid >> 2;
    int g = lane >> 2, tig = lane & 3;
    float c[8][4];
#pragma unroll
    for (int i = 0; i < 8; i++) { c[i][0] = c[i][1] = c[i][2] = c[i][3] = 0.f; }

    for (int kk = 0; kk < 24; kk++) {
        int seg = kk >> 3;
        int krel = (kk & 7) * 16;
        const float* src = (seg == 0) ? d_gacc : (seg == 1) ? d_sacc : x;
        const float* wseg = (seg == 0) ? Wp : (seg == 1) ? d_B : d_C;
        int r = tid >> 2, k4 = (tid & 3) << 2;
        int gr = rowBase + r;
        float4 v = make_float4(0.f, 0.f, 0.f, 0.f);
        if (gr < n) v = *(const float4*)&src[(size_t)gr * DIM + krel + k4];
        u.s.xs[r][k4 + 0] = f2tf(v.x); u.s.xs[r][k4 + 1] = f2tf(v.y);
        u.s.xs[r][k4 + 2] = f2tf(v.z); u.s.xs[r][k4 + 3] = f2tf(v.w);
#pragma unroll
        for (int i = 0; i < 2; i++) {
            int id = tid + i * 256;
            int wr = id >> 5, wc = (id & 31) << 2;
            float4 w4 = *(const float4*)&wseg[(size_t)(krel + wr) * DIM + wc];
            u.s.ws[wr][wc + 0] = f2tf(w4.x); u.s.ws[wr][wc + 1] = f2tf(w4.y);
            u.s.ws[wr][wc + 2] = f2tf(w4.z); u.s.ws[wr][wc + 3] = f2tf(w4.w);
        }
        __syncthreads();
#pragma unroll
        for (int k8 = 0; k8 < 16; k8 += 8) {
            unsigned a0 = __float_as_uint(u.s.xs[warpM * 16 + g][k8 + tig]);
            unsigned a1 = __float_as_uint(u.s.xs[warpM * 16 + g + 8][k8 + tig]);
            unsigned a2 = __float_as_uint(u.s.xs[warpM * 16 + g][k8 + tig + 4]);
            unsigned a3 = __float_as_uint(u.s.xs[warpM * 16 + g + 8][k8 + tig + 4]);
#pragma unroll
            for (int n8 = 0; n8 < 8; n8++) {
                int cb = warpN * 64 + n8 * 8 + g;
                unsigned b0 = __float_as_uint(u.s.ws[k8 + tig][cb]);
                unsigned b1 = __float_as_uint(u.s.ws[k8 + tig + 4][cb]);
                mma_tf32(c[n8], a0, a1, a2, a3, b0, b1);
            }
        }
        __syncthreads();
    }
    // dump frags
    {
        int rb = warpM * 16, cb = warpN * 64;
#pragma unroll
        for (int n8 = 0; n8 < 8; n8++) {
            int cc = cb + n8 * 8 + 2 * tig;
            u.ot[rb + g][cc] = c[n8][0];     u.ot[rb + g][cc + 1] = c[n8][1];
            u.ot[rb + g + 8][cc] = c[n8][2]; u.ot[rb + g + 8][cc + 1] = c[n8][3];
        }
    }
    __syncthreads();
    // epilogue: + dvec, LayerNorm per row
    int tx = lane, ty = wid;
    float4 dv = *(const float4*)&d_dvec[tx << 2];
    float4 gm = *(const float4*)&gamma[tx << 2];
    float4 bt = *(const float4*)&beta[tx << 2];
#pragma unroll
    for (int r8 = 0; r8 < 8; r8++) {
        float4 av = *(float4*)&u.ot[ty * 8 + r8][tx << 2];
        float v0 = av.x + dv.x, v1 = av.y + dv.y;
        float v2 = av.z + dv.z, v3 = av.w + dv.w;
        float sum = v0 + v1 + v2 + v3;
        float sq = v0 * v0 + v1 * v1 + v2 * v2 + v3 * v3;
#pragma unroll
        for (int o = 16; o; o >>= 1) {
            sum += __shfl_xor_sync(0xffffffffu, sum, o);
            sq  += __shfl_xor_sync(0xffffffffu, sq, o);
        }
        float mu = sum * (1.f / 128.f);
        float var = sq * (1.f / 128.f) - mu * mu;
        float rstd = rsqrtf(var + 1e-5f);
        int gr = rowBase + ty * 8 + r8;
        if (gr < n) {
            float4 o4;
            o4.x = (v0 - mu) * rstd * gm.x + bt.x;
            o4.y = (v1 - mu) * rstd * gm.y + bt.y;
            o4.z = (v2 - mu) * rstd * gm.z + bt.z;
            o4.w = (v3 - mu) * rstd * gm.w + bt.w;
            *(float4*)&out[(size_t)gr * DIM + (tx << 2)] = o4;
        }
    }
}

extern "C" void kernel_launch(void* const* d_in, const int* in_sizes, int n_in,
                              void* d_out, int out_size) {
    const float* x       = (const float*)d_in[0];
    const void*  eidx    = d_in[1];
    const float* W_gat   = (const float*)d_in[2];
    const float* att_src = (const float*)d_in[3];
    const float* att_dst = (const float*)d_in[4];
    const float* b_gat   = (const float*)d_in[5];
    const float* W_l     = (const float*)d_in[6];
    const float* b_l     = (const float*)d_in[7];
    const float* W_r     = (const float*)d_in[8];
    const float* W_proj  = (const float*)d_in[9];
    const float* b_proj  = (const float*)d_in[10];
    const float* gamma   = (const float*)d_in[11];
    const float* beta    = (const float*)d_in[12];

    int n = in_sizes[0] / DIM;
    int E = in_sizes[1] / 2;

    k_detect<<<1, 32>>>((const unsigned*)eidx);                             // 1
    k_zero_fill<<<(n + 255) / 256, 256>>>(n);                               // 2
    k_gemm_h<<<(n + 63) / 64, 256>>>(x, W_gat, att_src, att_dst, n);        // 3
    k_scatter<<<(E + 255) / 256, 256>>>((const int*)eidx, E);               // 4
    k_xcvt<<<(n * (DIM / 4) + 255) / 256, 256>>>(x, n);                     // 5
    k_gather<<<(n * 32 + 255) / 256, 256>>>(b_gat, n);                      // 6 <- ncu capture
    k_prep<<<5, 256>>>(W_l, W_r, b_l, W_proj, b_proj);                      // 7
    k_final<<<(n + 63) / 64, 256>>>(x, W_proj, gamma, beta, (float*)d_out, n);  // 8
}